// round 15
// baseline (speedup 1.0000x reference)
#include <cuda_runtime.h>
#include <cuda_fp16.h>
#include <math.h>
#include <cstdint>

// Problem constants
#define N_IN   100000
#define N_OUT  200000
#define C_IN   128
#define C_OUT  64
#define KOFF   27
#define MPAIRS 100000
#define BN_EPS 1e-5f

// Tiling: warp-chunks of 32 pairs; 3125 chunks per k (exact, no tail).
#define NCHUNKS      3125
#define BLOCKS_X     16          // R13 sweet spot (21 regressed: clock/power)
#define WARPS_PER_B  4
#define STREAMS      (BLOCKS_X * WARPS_PER_B)   // 64 warp-streams per k

// SMEM: B (w fp16 [128k x 64n], 144B row stride)
#define B_STRIDE   144
#define SMEM_TOTAL 18432

// Pre-converted x, fp16, fragment-permuted, per-lane-contiguous:
// per row 128 fp16 (256B); element order: [q][ks][4] with the 4-group =
// cols {16ks+2q, 16ks+2q+1, 16ks+2q+8, 16ks+2q+9}.
__device__ __align__(16) uint16_t g_xh[(size_t)N_IN * C_IN];

// BN scratch
__device__ float g_sum[C_OUT];
__device__ float g_sq[C_OUT];

// ======================= helpers =======================
__device__ __forceinline__ uint32_t smem_u32(const void* p) {
    uint32_t a;
    asm("{ .reg .u64 t; cvta.to.shared.u64 t, %1; cvt.u32.u64 %0, t; }"
        : "=r"(a) : "l"(p));
    return a;
}
__device__ __forceinline__ uint32_t cvt_f16x2(float lo, float hi) {
    uint32_t r;
    asm("cvt.rn.f16x2.f32 %0, %1, %2;" : "=r"(r) : "f"(hi), "f"(lo));
    return r;
}
__device__ __forceinline__ void ldmx4t(uint32_t r[4], uint32_t addr) {
    asm volatile("ldmatrix.sync.aligned.m8n8.x4.trans.shared.b16 {%0,%1,%2,%3}, [%4];"
                 : "=r"(r[0]), "=r"(r[1]), "=r"(r[2]), "=r"(r[3]) : "r"(addr));
}
__device__ __forceinline__ void mma_fp16(float* c, uint32_t a0, uint32_t a1,
                                         uint32_t a2, uint32_t a3,
                                         uint32_t b0, uint32_t b1) {
    asm volatile(
        "mma.sync.aligned.m16n8k16.row.col.f32.f16.f16.f32 "
        "{%0,%1,%2,%3}, {%4,%5,%6,%7}, {%8,%9}, {%0,%1,%2,%3};"
        : "+f"(c[0]), "+f"(c[1]), "+f"(c[2]), "+f"(c[3])
        : "r"(a0), "r"(a1), "r"(a2), "r"(a3), "r"(b0), "r"(b1));
}

// Channel permutation: GEMM n-index -> real output channel.
// n = nt*8 + 2q + bit  ->  real = q*16 + nt*2 + bit
// Makes each thread's 16 channels per row contiguous -> RED.v4 scatter.
__device__ __forceinline__ int perm_n(int n) {
    return ((n >> 1) & 3) * 16 + ((n >> 3) << 1) + (n & 1);
}

// ---------------------------------------------------------------------------
// Prep: convert x to fp16 in per-lane-contiguous permuted layout.
// ---------------------------------------------------------------------------
__global__ void prep_kernel(const float* __restrict__ x) {
    if (blockIdx.x == 0 && threadIdx.x < C_OUT) {
        g_sum[threadIdx.x] = 0.f;
        g_sq[threadIdx.x]  = 0.f;
    }
    const int t = blockIdx.x * blockDim.x + threadIdx.x;
    if (t >= N_IN * 32) return;
    const int row = t >> 5;
    const int ks  = (t & 31) >> 2;
    const int q   = t & 3;

    const float* xr = x + (size_t)row * C_IN + ks * 16 + 2 * q;
    float2 va = *(const float2*)xr;        // cols c, c+1
    float2 vb = *(const float2*)(xr + 8);  // cols c+8, c+9

    uint2 gr = make_uint2(cvt_f16x2(va.x, va.y), cvt_f16x2(vb.x, vb.y));
    *(uint2*)(g_xh + (size_t)row * 128 + q * 32 + ks * 4) = gr;
}

// ---------------------------------------------------------------------------
// Conv: single-term fp16 mma.sync gather-GEMM-scatter.
// grid = (16, 27); block = 128 (4 warps); 4 CTA/SM.
// Scatter uses RED.v4 thanks to the channel permutation.
// ---------------------------------------------------------------------------
__global__ void __launch_bounds__(128, 4) conv_mma_kernel(
    const float* __restrict__ weight,
    const int*   __restrict__ in_map,
    const int*   __restrict__ out_map,
    float*       __restrict__ out)
{
    extern __shared__ unsigned char smemc[];
    const int tid  = threadIdx.x;
    const int lane = tid & 31;
    const int wid  = tid >> 5;
    const int k    = blockIdx.y;

    // ---- stage weight[k] as fp16 into SMEM B tile (perm applied) ----
    {
        const float* wk = weight + (size_t)k * C_IN * C_OUT;
        for (int i = tid; i < C_IN * C_OUT; i += 128) {
            const int ci = i >> 6;
            const int n  = i & 63;
            *(unsigned short*)(smemc + ci * B_STRIDE + n * 2) =
                __half_as_ushort(__float2half_rn(wk[ci * C_OUT + perm_n(n)]));
        }
    }
    __syncthreads();

    const uint32_t sbase = smem_u32(smemc);
    const uint32_t bPart =
        (uint32_t)(((lane & 7) + ((lane >> 3) & 1) * 8) * B_STRIDE + (lane >> 4) * 16);
    const uint32_t bBase = sbase + bPart;

    const int q = lane & 3;
    const int g = blockIdx.x * WARPS_PER_B + wid;
    const uint16_t* xq = g_xh + q * 32;

    // prologue: first chunk's maps
    int cur_ir = 0, cur_or = 0;
    if (g < NCHUNKS) {
        const int gi0 = k * MPAIRS + g * 32 + lane;
        cur_ir = in_map[gi0];
        cur_or = out_map[gi0];
    }

    for (int c = g; c < NCHUNKS; c += STREAMS) {
        // prefetch next chunk's maps behind this chunk's MMA work
        int nxt_ir = 0, nxt_or = 0;
        const int nc = c + STREAMS;
        if (nc < NCHUNKS) {
            const int gin = k * MPAIRS + nc * 32 + lane;
            nxt_ir = in_map[gin];
            nxt_or = out_map[gin];
        }

        // Fragment row pointers: [ms][rowhalf]
        const uint16_t* pa[2][2];
        #pragma unroll
        for (int ms = 0; ms < 2; ms++) {
            const int rlo = __shfl_sync(0xffffffffu, cur_ir, ms * 16 + (lane >> 2));
            const int rhi = __shfl_sync(0xffffffffu, cur_ir, ms * 16 + 8 + (lane >> 2));
            pa[ms][0] = xq + (size_t)rlo * 128;
            pa[ms][1] = xq + (size_t)rhi * 128;
        }

        float acc[2][8][4];
        #pragma unroll
        for (int ms = 0; ms < 2; ms++)
            #pragma unroll
            for (int nt = 0; nt < 8; nt++)
                #pragma unroll
                for (int u = 0; u < 4; u++) acc[ms][nt][u] = 0.f;

        #pragma unroll
        for (int i = 0; i < 4; i++) {      // ks pairs: (2i, 2i+1)
            uint4 lo[2], hi[2];
            #pragma unroll
            for (int ms = 0; ms < 2; ms++) {
                lo[ms] = *(const uint4*)(pa[ms][0] + i * 8);
                hi[ms] = *(const uint4*)(pa[ms][1] + i * 8);
            }
            #pragma unroll
            for (int s = 0; s < 2; s++) {
                const int ks = 2 * i + s;
                uint32_t B[4][4];
                #pragma unroll
                for (int ng = 0; ng < 4; ng++)
                    ldmx4t(B[ng], bBase + ks * 16 * B_STRIDE + ng * 32);

                #pragma unroll
                for (int ms = 0; ms < 2; ms++) {
                    const uint32_t a0 = s ? lo[ms].z : lo[ms].x;
                    const uint32_t a2 = s ? lo[ms].w : lo[ms].y;
                    const uint32_t a1 = s ? hi[ms].z : hi[ms].x;
                    const uint32_t a3 = s ? hi[ms].w : hi[ms].y;
                    #pragma unroll
                    for (int nt = 0; nt < 8; nt++) {
                        const int ng = nt >> 1;
                        const int pp = (nt & 1) * 2;
                        mma_fp16(acc[ms][nt], a0, a1, a2, a3, B[ng][pp], B[ng][pp + 1]);
                    }
                }
            }
        }

        // ---- scatter-add: thread owns real chs q*16..q*16+15 per row ----
        #pragma unroll
        for (int ms = 0; ms < 2; ms++) {
            const int row0 = ms * 16 + (lane >> 2);
            const int or0 = __shfl_sync(0xffffffffu, cur_or, row0);
            const int or1 = __shfl_sync(0xffffffffu, cur_or, row0 + 8);
            float* d0 = out + (size_t)or0 * C_OUT + q * 16;
            float* d1 = out + (size_t)or1 * C_OUT + q * 16;
            #pragma unroll
            for (int ng = 0; ng < 4; ng++) {
                // real chs q*16 + ng*4 .. +3  = acc[ms][2ng][0..1], acc[ms][2ng+1][0..1]
                asm volatile("red.global.add.v4.f32 [%0], {%1, %2, %3, %4};"
                             :: "l"(d0 + ng * 4),
                                "f"(acc[ms][2*ng][0]), "f"(acc[ms][2*ng][1]),
                                "f"(acc[ms][2*ng+1][0]), "f"(acc[ms][2*ng+1][1])
                             : "memory");
                asm volatile("red.global.add.v4.f32 [%0], {%1, %2, %3, %4};"
                             :: "l"(d1 + ng * 4),
                                "f"(acc[ms][2*ng][2]), "f"(acc[ms][2*ng][3]),
                                "f"(acc[ms][2*ng+1][2]), "f"(acc[ms][2*ng+1][3])
                             : "memory");
            }
        }

        cur_ir = nxt_ir;
        cur_or = nxt_or;
    }
}

// ---------------------------------------------------------------------------
// Per-channel sum / sumsq over [N_OUT, 64]  (R13 known-good version)
// ---------------------------------------------------------------------------
__global__ void stats_kernel(const float* __restrict__ out) {
    const int c    = threadIdx.x & 63;
    const int rsub = threadIdx.x >> 6;
    float s = 0.f, q = 0.f;
    for (int r = blockIdx.x * 4 + rsub; r < N_OUT; r += gridDim.x * 4) {
        float v = out[(size_t)r * C_OUT + c];
        s += v;
        q = fmaf(v, v, q);
    }
    __shared__ float ssh[256];
    __shared__ float qsh[256];
    ssh[threadIdx.x] = s;
    qsh[threadIdx.x] = q;
    __syncthreads();
    if (rsub == 0) {
        s = ssh[c] + ssh[c + 64] + ssh[c + 128] + ssh[c + 192];
        q = qsh[c] + qsh[c + 64] + qsh[c + 128] + qsh[c + 192];
        atomicAdd(&g_sum[c], s);
        atomicAdd(&g_sq[c], q);
    }
}

// ---------------------------------------------------------------------------
// Normalize + ReLU with inline BN finalize
// ---------------------------------------------------------------------------
__global__ void norm_kernel(float* __restrict__ out,
                            const float* __restrict__ gamma,
                            const float* __restrict__ beta,
                            long long n4) {
    __shared__ float s_scale[C_OUT];
    __shared__ float s_bias[C_OUT];
    if (threadIdx.x < C_OUT) {
        const int c = threadIdx.x;
        const float invn = 1.0f / (float)N_OUT;
        float mean = g_sum[c] * invn;
        float var  = g_sq[c] * invn - mean * mean;
        float sc   = gamma[c] * rsqrtf(var + BN_EPS);
        s_scale[c] = sc;
        s_bias[c]  = beta[c] - mean * sc;
    }
    __syncthreads();
    long long i = (long long)blockIdx.x * blockDim.x + threadIdx.x;
    if (i < n4) {
        float4 v = ((float4*)out)[i];
        int c0 = (int)((i * 4) & 63);
        v.x = fmaxf(fmaf(v.x, s_scale[c0 + 0], s_bias[c0 + 0]), 0.f);
        v.y = fmaxf(fmaf(v.y, s_scale[c0 + 1], s_bias[c0 + 1]), 0.f);
        v.z = fmaxf(fmaf(v.z, s_scale[c0 + 2], s_bias[c0 + 2]), 0.f);
        v.w = fmaxf(fmaf(v.w, s_scale[c0 + 3], s_bias[c0 + 3]), 0.f);
        ((float4*)out)[i] = v;
    }
}

// ---------------------------------------------------------------------------
// kernel_launch — graph-capturable, default stream
// Inputs (metadata order): x, weight, gamma, beta, in_map, out_map
// ---------------------------------------------------------------------------
extern "C" void kernel_launch(void* const* d_in, const int* in_sizes, int n_in,
                              void* d_out, int out_size)
{
    const float* x       = (const float*)d_in[0];
    const float* weight  = (const float*)d_in[1];
    const float* gamma   = (const float*)d_in[2];
    const float* beta    = (const float*)d_in[3];
    const int*   in_map  = (const int*)d_in[4];
    const int*   out_map = (const int*)d_in[5];
    float*       out     = (float*)d_out;

    cudaMemsetAsync(out, 0, (size_t)out_size * sizeof(float));

    prep_kernel<<<(N_IN * 32 + 255) / 256, 256>>>(x);

    dim3 cgrid(BLOCKS_X, KOFF);
    conv_mma_kernel<<<cgrid, 128, SMEM_TOTAL>>>(weight, in_map, out_map, out);

    stats_kernel<<<592, 256>>>(out);

    long long n4 = (long long)out_size / 4;
    norm_kernel<<<(int)((n4 + 255) / 256), 256>>>(out, gamma, beta, n4);
}

// round 17
// speedup vs baseline: 1.5382x; 1.5382x over previous
#include <cuda_runtime.h>
#include <cuda_fp16.h>
#include <math.h>
#include <cstdint>

// Problem constants
#define N_IN   100000
#define N_OUT  200000
#define C_IN   128
#define C_OUT  64
#define KOFF   27
#define MPAIRS 100000
#define BN_EPS 1e-5f

// Tiling: warp-chunks of 32 pairs; 3125 chunks per k (exact, no tail).
#define NCHUNKS      3125
#define BLOCKS_X     16
#define WARPS_PER_B  4
#define STREAMS      (BLOCKS_X * WARPS_PER_B)   // 64 warp-streams per k

// SMEM: B (w fp16 [128k x 64n], 144B row stride)
#define B_STRIDE   144
#define SMEM_TOTAL 18432

// Pre-converted x, fp16, fragment-permuted, per-lane-contiguous:
// per row 128 fp16 (256B); element order: [q][ks][4] with the 4-group =
// cols {16ks+2q, 16ks+2q+1, 16ks+2q+8, 16ks+2q+9}.
__device__ __align__(16) uint16_t g_xh[(size_t)N_IN * C_IN];

// BN scratch
__device__ float g_sum[C_OUT];
__device__ float g_sq[C_OUT];

// ======================= helpers =======================
__device__ __forceinline__ uint32_t smem_u32(const void* p) {
    uint32_t a;
    asm("{ .reg .u64 t; cvta.to.shared.u64 t, %1; cvt.u32.u64 %0, t; }"
        : "=r"(a) : "l"(p));
    return a;
}
__device__ __forceinline__ uint32_t cvt_f16x2(float lo, float hi) {
    uint32_t r;
    asm("cvt.rn.f16x2.f32 %0, %1, %2;" : "=r"(r) : "f"(hi), "f"(lo));
    return r;
}
__device__ __forceinline__ void ldmx4t(uint32_t r[4], uint32_t addr) {
    asm volatile("ldmatrix.sync.aligned.m8n8.x4.trans.shared.b16 {%0,%1,%2,%3}, [%4];"
                 : "=r"(r[0]), "=r"(r[1]), "=r"(r[2]), "=r"(r[3]) : "r"(addr));
}
__device__ __forceinline__ void mma_fp16(float* c, uint32_t a0, uint32_t a1,
                                         uint32_t a2, uint32_t a3,
                                         uint32_t b0, uint32_t b1) {
    asm volatile(
        "mma.sync.aligned.m16n8k16.row.col.f32.f16.f16.f32 "
        "{%0,%1,%2,%3}, {%4,%5,%6,%7}, {%8,%9}, {%0,%1,%2,%3};"
        : "+f"(c[0]), "+f"(c[1]), "+f"(c[2]), "+f"(c[3])
        : "r"(a0), "r"(a1), "r"(a2), "r"(a3), "r"(b0), "r"(b1));
}

// Channel permutation: GEMM n-index -> real output channel.
// n = nt*8 + 2q + bit  ->  real = q*16 + nt*2 + bit
// Makes each thread's 16 channels per row contiguous -> RED.v4 scatter.
__device__ __forceinline__ int perm_n(int n) {
    return ((n >> 1) & 3) * 16 + ((n >> 3) << 1) + (n & 1);
}

// ---------------------------------------------------------------------------
// Prep: convert x to fp16 in per-lane-contiguous permuted layout.
// ---------------------------------------------------------------------------
__global__ void prep_kernel(const float* __restrict__ x) {
    if (blockIdx.x == 0 && threadIdx.x < C_OUT) {
        g_sum[threadIdx.x] = 0.f;
        g_sq[threadIdx.x]  = 0.f;
    }
    const int t = blockIdx.x * blockDim.x + threadIdx.x;
    if (t >= N_IN * 32) return;
    const int row = t >> 5;
    const int ks  = (t & 31) >> 2;
    const int q   = t & 3;

    const float* xr = x + (size_t)row * C_IN + ks * 16 + 2 * q;
    float2 va = *(const float2*)xr;        // cols c, c+1
    float2 vb = *(const float2*)(xr + 8);  // cols c+8, c+9

    uint2 gr = make_uint2(cvt_f16x2(va.x, va.y), cvt_f16x2(vb.x, vb.y));
    *(uint2*)(g_xh + (size_t)row * 128 + q * 32 + ks * 4) = gr;
}

// ---------------------------------------------------------------------------
// Conv: single-term fp16 mma.sync gather-GEMM-scatter.
// grid = (16, 27); block = 128 (4 warps); 3 CTA/SM (reg headroom so the
// whole 16x LDG.128 A tile hoists ahead of the 128-HMMA mainloop).
// Scatter uses RED.v4 via the channel permutation.
// ---------------------------------------------------------------------------
__global__ void __launch_bounds__(128, 3) conv_mma_kernel(
    const float* __restrict__ weight,
    const int*   __restrict__ in_map,
    const int*   __restrict__ out_map,
    float*       __restrict__ out)
{
    extern __shared__ unsigned char smemc[];
    const int tid  = threadIdx.x;
    const int lane = tid & 31;
    const int wid  = tid >> 5;
    const int k    = blockIdx.y;

    // ---- stage weight[k] as fp16 into SMEM B tile (perm applied) ----
    {
        const float* wk = weight + (size_t)k * C_IN * C_OUT;
        for (int i = tid; i < C_IN * C_OUT; i += 128) {
            const int ci = i >> 6;
            const int n  = i & 63;
            *(unsigned short*)(smemc + ci * B_STRIDE + n * 2) =
                __half_as_ushort(__float2half_rn(wk[ci * C_OUT + perm_n(n)]));
        }
    }
    __syncthreads();

    const uint32_t sbase = smem_u32(smemc);
    const uint32_t bPart =
        (uint32_t)(((lane & 7) + ((lane >> 3) & 1) * 8) * B_STRIDE + (lane >> 4) * 16);
    const uint32_t bBase = sbase + bPart;

    const int q = lane & 3;
    const int g = blockIdx.x * WARPS_PER_B + wid;
    const uint16_t* xq = g_xh + q * 32;

    // prologue: first chunk's maps
    int cur_ir = 0, cur_or = 0;
    if (g < NCHUNKS) {
        const int gi0 = k * MPAIRS + g * 32 + lane;
        cur_ir = in_map[gi0];
        cur_or = out_map[gi0];
    }

    for (int c = g; c < NCHUNKS; c += STREAMS) {
        // prefetch next chunk's maps behind this chunk's work
        int nxt_ir = 0, nxt_or = 0;
        const int nc = c + STREAMS;
        if (nc < NCHUNKS) {
            const int gin = k * MPAIRS + nc * 32 + lane;
            nxt_ir = in_map[gin];
            nxt_or = out_map[gin];
        }

        // Fragment row pointers: [ms][rowhalf]
        const uint16_t* pa[2][2];
        #pragma unroll
        for (int ms = 0; ms < 2; ms++) {
            const int rlo = __shfl_sync(0xffffffffu, cur_ir, ms * 16 + (lane >> 2));
            const int rhi = __shfl_sync(0xffffffffu, cur_ir, ms * 16 + 8 + (lane >> 2));
            pa[ms][0] = xq + (size_t)rlo * 128;
            pa[ms][1] = xq + (size_t)rhi * 128;
        }

        // ---- issue the ENTIRE A tile up front: 16x LDG.128, MLP=16 ----
        uint4 lo[4][2], hi[4][2];    // [i][ms]
        #pragma unroll
        for (int i = 0; i < 4; i++) {
            #pragma unroll
            for (int ms = 0; ms < 2; ms++) {
                lo[i][ms] = *(const uint4*)(pa[ms][0] + i * 8);
                hi[i][ms] = *(const uint4*)(pa[ms][1] + i * 8);
            }
        }

        float acc[2][8][4];
        #pragma unroll
        for (int ms = 0; ms < 2; ms++)
            #pragma unroll
            for (int nt = 0; nt < 8; nt++)
                #pragma unroll
                for (int u = 0; u < 4; u++) acc[ms][nt][u] = 0.f;

        #pragma unroll
        for (int i = 0; i < 4; i++) {      // ks pairs: (2i, 2i+1)
            #pragma unroll
            for (int s = 0; s < 2; s++) {
                const int ks = 2 * i + s;
                uint32_t B[4][4];
                #pragma unroll
                for (int ng = 0; ng < 4; ng++)
                    ldmx4t(B[ng], bBase + ks * 16 * B_STRIDE + ng * 32);

                #pragma unroll
                for (int ms = 0; ms < 2; ms++) {
                    const uint32_t a0 = s ? lo[i][ms].z : lo[i][ms].x;
                    const uint32_t a2 = s ? lo[i][ms].w : lo[i][ms].y;
                    const uint32_t a1 = s ? hi[i][ms].z : hi[i][ms].x;
                    const uint32_t a3 = s ? hi[i][ms].w : hi[i][ms].y;
                    #pragma unroll
                    for (int nt = 0; nt < 8; nt++) {
                        const int ng = nt >> 1;
                        const int pp = (nt & 1) * 2;
                        mma_fp16(acc[ms][nt], a0, a1, a2, a3, B[ng][pp], B[ng][pp + 1]);
                    }
                }
            }
        }

        // ---- scatter-add: thread owns real chs q*16..q*16+15 per row ----
        #pragma unroll
        for (int ms = 0; ms < 2; ms++) {
            const int row0 = ms * 16 + (lane >> 2);
            const int or0 = __shfl_sync(0xffffffffu, cur_or, row0);
            const int or1 = __shfl_sync(0xffffffffu, cur_or, row0 + 8);
            float* d0 = out + (size_t)or0 * C_OUT + q * 16;
            float* d1 = out + (size_t)or1 * C_OUT + q * 16;
            #pragma unroll
            for (int ng = 0; ng < 4; ng++) {
                asm volatile("red.global.add.v4.f32 [%0], {%1, %2, %3, %4};"
                             :: "l"(d0 + ng * 4),
                                "f"(acc[ms][2*ng][0]), "f"(acc[ms][2*ng][1]),
                                "f"(acc[ms][2*ng+1][0]), "f"(acc[ms][2*ng+1][1])
                             : "memory");
                asm volatile("red.global.add.v4.f32 [%0], {%1, %2, %3, %4};"
                             :: "l"(d1 + ng * 4),
                                "f"(acc[ms][2*ng][2]), "f"(acc[ms][2*ng][3]),
                                "f"(acc[ms][2*ng+1][2]), "f"(acc[ms][2*ng+1][3])
                             : "memory");
            }
        }

        cur_ir = nxt_ir;
        cur_or = nxt_or;
    }
}

// ---------------------------------------------------------------------------
// Per-channel sum / sumsq over [N_OUT, 64]
// ---------------------------------------------------------------------------
__global__ void stats_kernel(const float* __restrict__ out) {
    const int c    = threadIdx.x & 63;
    const int rsub = threadIdx.x >> 6;
    float s = 0.f, q = 0.f;
    for (int r = blockIdx.x * 4 + rsub; r < N_OUT; r += gridDim.x * 4) {
        float v = out[(size_t)r * C_OUT + c];
        s += v;
        q = fmaf(v, v, q);
    }
    __shared__ float ssh[256];
    __shared__ float qsh[256];
    ssh[threadIdx.x] = s;
    qsh[threadIdx.x] = q;
    __syncthreads();
    if (rsub == 0) {
        s = ssh[c] + ssh[c + 64] + ssh[c + 128] + ssh[c + 192];
        q = qsh[c] + qsh[c + 64] + qsh[c + 128] + qsh[c + 192];
        atomicAdd(&g_sum[c], s);
        atomicAdd(&g_sq[c], q);
    }
}

// ---------------------------------------------------------------------------
// Normalize + ReLU with inline BN finalize
// ---------------------------------------------------------------------------
__global__ void norm_kernel(float* __restrict__ out,
                            const float* __restrict__ gamma,
                            const float* __restrict__ beta,
                            long long n4) {
    __shared__ float s_scale[C_OUT];
    __shared__ float s_bias[C_OUT];
    if (threadIdx.x < C_OUT) {
        const int c = threadIdx.x;
        const float invn = 1.0f / (float)N_OUT;
        float mean = g_sum[c] * invn;
        float var  = g_sq[c] * invn - mean * mean;
        float sc   = gamma[c] * rsqrtf(var + BN_EPS);
        s_scale[c] = sc;
        s_bias[c]  = beta[c] - mean * sc;
    }
    __syncthreads();
    long long i = (long long)blockIdx.x * blockDim.x + threadIdx.x;
    if (i < n4) {
        float4 v = ((float4*)out)[i];
        int c0 = (int)((i * 4) & 63);
        v.x = fmaxf(fmaf(v.x, s_scale[c0 + 0], s_bias[c0 + 0]), 0.f);
        v.y = fmaxf(fmaf(v.y, s_scale[c0 + 1], s_bias[c0 + 1]), 0.f);
        v.z = fmaxf(fmaf(v.z, s_scale[c0 + 2], s_bias[c0 + 2]), 0.f);
        v.w = fmaxf(fmaf(v.w, s_scale[c0 + 3], s_bias[c0 + 3]), 0.f);
        ((float4*)out)[i] = v;
    }
}

// ---------------------------------------------------------------------------
// kernel_launch — graph-capturable, default stream
// Inputs (metadata order): x, weight, gamma, beta, in_map, out_map
// ---------------------------------------------------------------------------
extern "C" void kernel_launch(void* const* d_in, const int* in_sizes, int n_in,
                              void* d_out, int out_size)
{
    const float* x       = (const float*)d_in[0];
    const float* weight  = (const float*)d_in[1];
    const float* gamma   = (const float*)d_in[2];
    const float* beta    = (const float*)d_in[3];
    const int*   in_map  = (const int*)d_in[4];
    const int*   out_map = (const int*)d_in[5];
    float*       out     = (float*)d_out;

    cudaMemsetAsync(out, 0, (size_t)out_size * sizeof(float));

    prep_kernel<<<(N_IN * 32 + 255) / 256, 256>>>(x);

    dim3 cgrid(BLOCKS_X, KOFF);
    conv_mma_kernel<<<cgrid, 128, SMEM_TOTAL>>>(weight, in_map, out_map, out);

    stats_kernel<<<592, 256>>>(out);

    long long n4 = (long long)out_size / 4;
    norm_kernel<<<(int)((n4 + 255) / 256), 256>>>(out, gamma, beta, n4);
}